// round 15
// baseline (speedup 1.0000x reference)
#include <cuda_runtime.h>
#include <cuda_bf16.h>
#include <mma.h>
#include <cstdint>

using namespace nvcuda;

#define BB 64
#define CC 2048
#define DD 512
#define MM 128
#define NNEG 1920
#define TT 100
#define EPS 1e-6f

#define NT 128                 // n-tile per block
#define KCH 32                 // K elems per chunk
#define NCHUNK (DD / KCH)      // 16
#define LDT 40                 // operand tile leading dim (bf16): 80B rows
#define LDC 68                 // C leading dim (f32)
#define TILEPAIR (2 * 128 * LDT * 2)   // A+B tile pair bytes = 20480

// scratch (allocation-free rule: __device__ globals)
__device__ float g_inv[BB * CC];
__device__ unsigned long long g_best[BB * MM];   // (ordered_sim<<32)|(0x7FFFFFFF-n)

__device__ __forceinline__ unsigned ordered_f32(float v) {
    unsigned u = __float_as_uint(v);
    return (u & 0x80000000u) ? ~u : (u | 0x80000000u);
}

// ---------------------------------------------------------------------------
// K0: init scratch + output
// ---------------------------------------------------------------------------
__global__ void k0_init(float* out) {
    int i = blockIdx.x * blockDim.x + threadIdx.x;
    if (i < BB * MM) g_best[i] = 0ULL;
    if (i == 0) out[0] = 0.0f;
}

// ---------------------------------------------------------------------------
// K1: per-row inverse norms (streaming 256MB read)
// ---------------------------------------------------------------------------
__global__ __launch_bounds__(256) void k1_norm(const float* __restrict__ emb) {
    int row  = blockIdx.x * 8 + (threadIdx.x >> 5);
    int lane = threadIdx.x & 31;
    const float4* p = reinterpret_cast<const float4*>(emb + (size_t)row * DD);
    float ss = 0.0f;
#pragma unroll
    for (int q = 0; q < 4; q++) {
        float4 v = p[lane + 32 * q];
        ss += v.x * v.x + v.y * v.y + v.z * v.z + v.w * v.w;
    }
#pragma unroll
    for (int off = 16; off; off >>= 1)
        ss += __shfl_xor_sync(0xffffffffu, ss, off);
    if (lane == 0)
        g_inv[row] = 1.0f / fmaxf(sqrtf(ss), 1e-12f);
}

// ---------------------------------------------------------------------------
// K2: hard-negative mining, bf16 WMMA, register-prefetch + DOUBLE-BUFFERED
// smem operand tiles (one __syncthreads per chunk).
// Raw rows staged as bf16; scale applied in epilogue:
//   argmax_n sim[m][n] == argmax_n raw[m][n]*scB[n]   (ia[m]>0 dropped)
// Block = (batch blockIdx.y, n-tile of 128), 256 threads = 8 warps (2m x 4n).
// Safety of single sync: store to buf[c&1] at chunk c+2 happens after that
// warp passed sync_{c+1}, which implies ALL warps finished mma_c on buf[c&1].
// ---------------------------------------------------------------------------
__global__ __launch_bounds__(256, 2) void k2_mine(const float* __restrict__ emb,
                                                  const int* __restrict__ muc,
                                                  const int* __restrict__ non) {
    // 2 operand buffers (A+B pair each, 20480B) = 40960B; C overlay (34816B) fits
    __shared__ __align__(16) char sbuf[2 * TILEPAIR];
    __shared__ int   rA[MM];
    __shared__ int   rB[NT];
    __shared__ float scB[NT];

    float (*Csh)[LDC] = reinterpret_cast<float (*)[LDC]>(sbuf);   // epilogue overlay

    const int b   = blockIdx.y;
    const int n0  = blockIdx.x * NT;
    const int tid = threadIdx.x;
    const int warp   = tid >> 5;
    const int warp_m = warp >> 2;       // 0..1
    const int warp_n = warp & 3;        // 0..3

    if (tid < 128) {
        rA[tid] = muc[b * MM + tid];
    } else {
        int t2 = tid - 128;
        int r  = non[b * NNEG + n0 + t2];
        rB[t2]  = r;
        scB[t2] = g_inv[b * CC + r];
    }
    __syncthreads();

    // per-thread staging coordinates: 4 float4 per tile per chunk
    const float* embB = emb + (size_t)b * CC * DD;
    const float4* srcA[4];
    const float4* srcB[4];
    uint32_t dstoff[4];
#pragma unroll
    for (int u = 0; u < 4; u++) {
        int f    = tid + 256 * u;
        int row  = f >> 3;
        int colq = f & 7;
        srcA[u]   = reinterpret_cast<const float4*>(embB + (size_t)rA[row] * DD) + colq;
        srcB[u]   = reinterpret_cast<const float4*>(embB + (size_t)rB[row] * DD) + colq;
        dstoff[u] = row * (LDT * 2) + colq * 8;       // byte offset: 1 float4 -> 4 bf16 = 8B
    }

    wmma::fragment<wmma::accumulator, 16, 16, 16, float> acc[4][2];
#pragma unroll
    for (int i = 0; i < 4; i++)
#pragma unroll
        for (int j = 0; j < 2; j++)
            wmma::fill_fragment(acc[i][j], 0.0f);

    float4 pfa[4], pfb[4];
#pragma unroll
    for (int u = 0; u < 4; u++) { pfa[u] = srcA[u][0]; pfb[u] = srcB[u][0]; }

    for (int ch = 0; ch < NCHUNK; ch++) {
        char* base = sbuf + (ch & 1) * TILEPAIR;     // this chunk's buffer
        char* baseB = base + 128 * LDT * 2;
        // commit prefetched regs -> smem buf[ch&1] (no pre-sync: see header note)
#pragma unroll
        for (int u = 0; u < 4; u++) {
            __nv_bfloat162 alo = __floats2bfloat162_rn(pfa[u].x, pfa[u].y);
            __nv_bfloat162 ahi = __floats2bfloat162_rn(pfa[u].z, pfa[u].w);
            uint2 wa = { *reinterpret_cast<unsigned*>(&alo), *reinterpret_cast<unsigned*>(&ahi) };
            *reinterpret_cast<uint2*>(base + dstoff[u]) = wa;
            __nv_bfloat162 blo = __floats2bfloat162_rn(pfb[u].x, pfb[u].y);
            __nv_bfloat162 bhi = __floats2bfloat162_rn(pfb[u].z, pfb[u].w);
            uint2 wb = { *reinterpret_cast<unsigned*>(&blo), *reinterpret_cast<unsigned*>(&bhi) };
            *reinterpret_cast<uint2*>(baseB + dstoff[u]) = wb;
        }
        __syncthreads();               // publish tiles (single sync per chunk)
        // issue next chunk's loads; latency overlaps the mma phase below
        if (ch + 1 < NCHUNK) {
            int ko = (ch + 1) * (KCH / 4);          // float4 offset
#pragma unroll
            for (int u = 0; u < 4; u++) { pfa[u] = srcA[u][ko]; pfb[u] = srcB[u][ko]; }
        }
        // mma phase on buf[ch&1]
        const __nv_bfloat16* As = reinterpret_cast<const __nv_bfloat16*>(base);
        const __nv_bfloat16* Bs = reinterpret_cast<const __nv_bfloat16*>(baseB);
#pragma unroll
        for (int kf = 0; kf < KCH / 16; kf++) {
            wmma::fragment<wmma::matrix_a, 16, 16, 16, __nv_bfloat16, wmma::row_major> af[4];
            wmma::fragment<wmma::matrix_b, 16, 16, 16, __nv_bfloat16, wmma::col_major> bf[2];
#pragma unroll
            for (int i = 0; i < 4; i++)
                wmma::load_matrix_sync(af[i], As + (warp_m * 64 + i * 16) * LDT + kf * 16, LDT);
#pragma unroll
            for (int j = 0; j < 2; j++)
                wmma::load_matrix_sync(bf[j], Bs + (warp_n * 32 + j * 16) * LDT + kf * 16, LDT);
#pragma unroll
            for (int i = 0; i < 4; i++)
#pragma unroll
                for (int j = 0; j < 2; j++)
                    wmma::mma_sync(acc[i][j], af[i], bf[j], acc[i][j]);
        }
    }

    // epilogue: two 64-col halves through Csh (overlays operand buffers)
    const int m_of = tid >> 1;
    const int part = tid & 1;
    float bestv = -1e30f;
    int   besti = 0;

#pragma unroll
    for (int half = 0; half < 2; half++) {
        __syncthreads();
        if ((warp_n >> 1) == half) {
#pragma unroll
            for (int i = 0; i < 4; i++)
#pragma unroll
                for (int j = 0; j < 2; j++)
                    wmma::store_matrix_sync(&Csh[warp_m * 64 + i * 16][(warp_n & 1) * 32 + j * 16],
                                            acc[i][j], LDC, wmma::mem_row_major);
        }
        __syncthreads();
#pragma unroll 8
        for (int jj = 0; jj < 32; jj++) {
            int  col = part * 32 + jj;
            float v  = Csh[m_of][col] * scB[half * 64 + col];
            int  gn  = n0 + half * 64 + col;
            if (v > bestv) { bestv = v; besti = gn; }   // ascending -> first max on ties
        }
    }
    // merge lane pairs (2t, 2t+1 share m)
    float ov = __shfl_xor_sync(0xffffffffu, bestv, 1);
    int   oi = __shfl_xor_sync(0xffffffffu, besti, 1);
    if (ov > bestv || (ov == bestv && oi < besti)) { bestv = ov; besti = oi; }
    if (part == 0) {
        unsigned long long key =
            ((unsigned long long)ordered_f32(bestv) << 32) |
            (unsigned)(0x7FFFFFFFu - besti);
        atomicMax(&g_best[b * MM + m_of], key);
    }
}

// ---------------------------------------------------------------------------
// K3: loss. One warp per (b,t): d_pos, d_neg (exact fp32), relu, atomicAdd.
// ---------------------------------------------------------------------------
__global__ __launch_bounds__(256) void k3_loss(const float* __restrict__ emb,
                                               const int* __restrict__ muc,
                                               const int* __restrict__ non,
                                               const int* __restrict__ anc,
                                               const int* __restrict__ pos,
                                               float* __restrict__ out) {
    int g    = blockIdx.x * blockDim.x + threadIdx.x;
    int w    = g >> 5;
    int lane = g & 31;
    if (w >= BB * TT) return;
    int b = w / TT;
    int t = w % TT;

    int m  = anc[b * TT + t];
    int ra = muc[b * MM + m];
    int rp = muc[b * MM + pos[b * TT + t]];

    unsigned long long key = g_best[b * MM + m];
    int n  = (int)(0x7FFFFFFFu - (unsigned)(key & 0xFFFFFFFFu));
    int rn = non[b * NNEG + n];

    const float4* pa = reinterpret_cast<const float4*>(emb + ((size_t)b * CC + ra) * DD);
    const float4* pp = reinterpret_cast<const float4*>(emb + ((size_t)b * CC + rp) * DD);
    const float4* pn = reinterpret_cast<const float4*>(emb + ((size_t)b * CC + rn) * DD);
    float ia  = g_inv[b * CC + ra];
    float ip  = g_inv[b * CC + rp];
    float in_ = g_inv[b * CC + rn];

    float ssp = 0.0f, ssn = 0.0f;
#pragma unroll
    for (int q = 0; q < 4; q++) {
        int o = lane + 32 * q;
        float4 va = pa[o];
        float4 vp = pp[o];
        float4 vn = pn[o];
        float d;
        d = va.x * ia - vp.x * ip + EPS;  ssp = fmaf(d, d, ssp);
        d = va.y * ia - vp.y * ip + EPS;  ssp = fmaf(d, d, ssp);
        d = va.z * ia - vp.z * ip + EPS;  ssp = fmaf(d, d, ssp);
        d = va.w * ia - vp.w * ip + EPS;  ssp = fmaf(d, d, ssp);
        d = va.x * ia - vn.x * in_ + EPS; ssn = fmaf(d, d, ssn);
        d = va.y * ia - vn.y * in_ + EPS; ssn = fmaf(d, d, ssn);
        d = va.z * ia - vn.z * in_ + EPS; ssn = fmaf(d, d, ssn);
        d = va.w * ia - vn.w * in_ + EPS; ssn = fmaf(d, d, ssn);
    }
#pragma unroll
    for (int off = 16; off; off >>= 1) {
        ssp += __shfl_xor_sync(0xffffffffu, ssp, off);
        ssn += __shfl_xor_sync(0xffffffffu, ssn, off);
    }
    if (lane == 0) {
        float term = sqrtf(ssp) - sqrtf(ssn) + 1.0f;   // margin = 1.0
        term = fmaxf(term, 0.0f);
        atomicAdd(out, term * (1.0f / (float)(BB * TT)));
    }
}

// ---------------------------------------------------------------------------
extern "C" void kernel_launch(void* const* d_in, const int* in_sizes, int n_in,
                              void* d_out, int out_size) {
    const float* emb = (const float*)d_in[0];
    const int*   muc = (const int*)d_in[1];
    const int*   non = (const int*)d_in[2];
    const int*   anc = (const int*)d_in[3];
    const int*   pos = (const int*)d_in[4];
    float* out = (float*)d_out;

    k0_init<<<(BB * MM + 255) / 256, 256>>>(out);
    k1_norm<<<(BB * CC) / 8, 256>>>(emb);
    dim3 g2(NNEG / NT, BB);
    k2_mine<<<g2, 256>>>(emb, muc, non);
    k3_loss<<<(BB * TT * 32 + 255) / 256, 256>>>(emb, muc, non, anc, pos, out);
}

// round 17
// speedup vs baseline: 1.4461x; 1.4461x over previous
#include <cuda_runtime.h>
#include <cuda_bf16.h>
#include <mma.h>
#include <cstdint>

using namespace nvcuda;

#define BB 64
#define CC 2048
#define DD 512
#define MM 128
#define NNEG 1920
#define TT 100
#define EPS 1e-6f

#define NT 64                  // n-tile per block (shrunk: acc 32 regs/thread)
#define KCH 32                 // K elems per chunk
#define NCHUNK (DD / KCH)      // 16
#define LDT 40                 // operand tile leading dim (bf16): 80B rows
#define LDC 68                 // C leading dim (f32)

// scratch (allocation-free rule: __device__ globals)
__device__ float g_inv[BB * CC];
__device__ unsigned long long g_best[BB * MM];   // (ordered_sim<<32)|(0x7FFFFFFF-n)

__device__ __forceinline__ unsigned ordered_f32(float v) {
    unsigned u = __float_as_uint(v);
    return (u & 0x80000000u) ? ~u : (u | 0x80000000u);
}

// ---------------------------------------------------------------------------
// K0: init scratch + output
// ---------------------------------------------------------------------------
__global__ void k0_init(float* out) {
    int i = blockIdx.x * blockDim.x + threadIdx.x;
    if (i < BB * MM) g_best[i] = 0ULL;
    if (i == 0) out[0] = 0.0f;
}

// ---------------------------------------------------------------------------
// K1: per-row inverse norms (streaming 256MB read)
// ---------------------------------------------------------------------------
__global__ __launch_bounds__(256) void k1_norm(const float* __restrict__ emb) {
    int row  = blockIdx.x * 8 + (threadIdx.x >> 5);
    int lane = threadIdx.x & 31;
    const float4* p = reinterpret_cast<const float4*>(emb + (size_t)row * DD);
    float ss = 0.0f;
#pragma unroll
    for (int q = 0; q < 4; q++) {
        float4 v = p[lane + 32 * q];
        ss += v.x * v.x + v.y * v.y + v.z * v.z + v.w * v.w;
    }
#pragma unroll
    for (int off = 16; off; off >>= 1)
        ss += __shfl_xor_sync(0xffffffffu, ss, off);
    if (lane == 0)
        g_inv[row] = 1.0f / fmaxf(sqrtf(ss), 1e-12f);
}

// ---------------------------------------------------------------------------
// K2: hard-negative mining, bf16 WMMA, register-prefetch, single-buffered
// (proven R14 structure). NT=64 + warp tile 32x32 shrinks live state
// (acc 32 regs) so __launch_bounds__(256,3) caps at 85 regs with headroom:
// 3 blocks/SM = 24 warps/SM (vs 16), extending the linear residency scaling
// measured R12->R14.
// Raw rows staged as bf16; scale applied in epilogue:
//   argmax_n sim[m][n] == argmax_n raw[m][n]*scB[n]   (ia[m]>0 dropped)
// Block = (batch blockIdx.y, n-tile of 64), 256 threads = 8 warps (4m x 2n).
// ---------------------------------------------------------------------------
__global__ __launch_bounds__(256, 3) void k2_mine(const float* __restrict__ emb,
                                                  const int* __restrict__ muc,
                                                  const int* __restrict__ non) {
    // operands: A 128xLDT (10240B) + B 64xLDT (5120B) = 15360B; C overlay 34816B
    __shared__ __align__(16) char sbuf[128 * LDC * 4];
    __shared__ int   rA[MM];
    __shared__ int   rB[NT];
    __shared__ float scB[NT];

    __nv_bfloat16* As = reinterpret_cast<__nv_bfloat16*>(sbuf);        // [128][LDT]
    __nv_bfloat16* Bs = As + 128 * LDT;                                // [64][LDT]
    float (*Csh)[LDC] = reinterpret_cast<float (*)[LDC]>(sbuf);        // overlay

    const int b   = blockIdx.y;
    const int n0  = blockIdx.x * NT;
    const int tid = threadIdx.x;
    const int warp   = tid >> 5;
    const int warp_m = warp >> 1;       // 0..3 -> m base warp_m*32
    const int warp_n = warp & 1;        // 0..1 -> n base warp_n*32

    if (tid < 128) {
        rA[tid] = muc[b * MM + tid];
    } else if (tid < 128 + NT) {
        int t2 = tid - 128;
        int r  = non[b * NNEG + n0 + t2];
        rB[t2]  = r;
        scB[t2] = g_inv[b * CC + r];
    }
    __syncthreads();

    // staging: per chunk A = 128x8 float4 (4/thread), B = 64x8 float4 (2/thread)
    const float* embB = emb + (size_t)b * CC * DD;
    const float4* srcA[4];
    const float4* srcB[2];
    uint32_t dstoffA[4], dstoffB[2];
#pragma unroll
    for (int u = 0; u < 4; u++) {
        int f    = tid + 256 * u;
        int row  = f >> 3;
        int colq = f & 7;
        srcA[u]    = reinterpret_cast<const float4*>(embB + (size_t)rA[row] * DD) + colq;
        dstoffA[u] = row * (LDT * 2) + colq * 8;      // 1 float4 -> 4 bf16 = 8B
    }
#pragma unroll
    for (int u = 0; u < 2; u++) {
        int f    = tid + 256 * u;
        int row  = f >> 3;                            // 0..63
        int colq = f & 7;
        srcB[u]    = reinterpret_cast<const float4*>(embB + (size_t)rB[row] * DD) + colq;
        dstoffB[u] = row * (LDT * 2) + colq * 8;
    }
    char* sAc = reinterpret_cast<char*>(As);
    char* sBc = reinterpret_cast<char*>(Bs);

    wmma::fragment<wmma::accumulator, 16, 16, 16, float> acc[2][2];
#pragma unroll
    for (int i = 0; i < 2; i++)
#pragma unroll
        for (int j = 0; j < 2; j++)
            wmma::fill_fragment(acc[i][j], 0.0f);

    float4 pfa[4], pfb[2];
#pragma unroll
    for (int u = 0; u < 4; u++) pfa[u] = srcA[u][0];
#pragma unroll
    for (int u = 0; u < 2; u++) pfb[u] = srcB[u][0];

    for (int ch = 0; ch < NCHUNK; ch++) {
        __syncthreads();               // previous mma phase done reading smem
        // commit prefetched regs -> smem (fp32 -> bf16)
#pragma unroll
        for (int u = 0; u < 4; u++) {
            __nv_bfloat162 lo = __floats2bfloat162_rn(pfa[u].x, pfa[u].y);
            __nv_bfloat162 hi = __floats2bfloat162_rn(pfa[u].z, pfa[u].w);
            uint2 w = { *reinterpret_cast<unsigned*>(&lo), *reinterpret_cast<unsigned*>(&hi) };
            *reinterpret_cast<uint2*>(sAc + dstoffA[u]) = w;
        }
#pragma unroll
        for (int u = 0; u < 2; u++) {
            __nv_bfloat162 lo = __floats2bfloat162_rn(pfb[u].x, pfb[u].y);
            __nv_bfloat162 hi = __floats2bfloat162_rn(pfb[u].z, pfb[u].w);
            uint2 w = { *reinterpret_cast<unsigned*>(&lo), *reinterpret_cast<unsigned*>(&hi) };
            *reinterpret_cast<uint2*>(sBc + dstoffB[u]) = w;
        }
        __syncthreads();               // tiles ready
        // issue next chunk's loads; latency overlaps the mma phase below
        if (ch + 1 < NCHUNK) {
            int ko = (ch + 1) * (KCH / 4);
#pragma unroll
            for (int u = 0; u < 4; u++) pfa[u] = srcA[u][ko];
#pragma unroll
            for (int u = 0; u < 2; u++) pfb[u] = srcB[u][ko];
        }
        // mma phase
#pragma unroll
        for (int kf = 0; kf < KCH / 16; kf++) {
            wmma::fragment<wmma::matrix_a, 16, 16, 16, __nv_bfloat16, wmma::row_major> af[2];
            wmma::fragment<wmma::matrix_b, 16, 16, 16, __nv_bfloat16, wmma::col_major> bf[2];
#pragma unroll
            for (int i = 0; i < 2; i++)
                wmma::load_matrix_sync(af[i], As + (warp_m * 32 + i * 16) * LDT + kf * 16, LDT);
#pragma unroll
            for (int j = 0; j < 2; j++)
                wmma::load_matrix_sync(bf[j], Bs + (warp_n * 32 + j * 16) * LDT + kf * 16, LDT);
#pragma unroll
            for (int i = 0; i < 2; i++)
#pragma unroll
                for (int j = 0; j < 2; j++)
                    wmma::mma_sync(acc[i][j], af[i], bf[j], acc[i][j]);
        }
    }

    // epilogue: single pass through Csh (128x64 fits), per-m argmax
    __syncthreads();
#pragma unroll
    for (int i = 0; i < 2; i++)
#pragma unroll
        for (int j = 0; j < 2; j++)
            wmma::store_matrix_sync(&Csh[warp_m * 32 + i * 16][warp_n * 32 + j * 16],
                                    acc[i][j], LDC, wmma::mem_row_major);
    __syncthreads();

    // compare value = raw_dot * scB[n] (ia[m] dropped: positive per-m constant)
    const int m_of = tid >> 1;          // 0..127
    const int part = tid & 1;           // 32 cols each
    float bestv = -1e30f;
    int   besti = 0;
#pragma unroll 8
    for (int jj = 0; jj < 32; jj++) {
        int  col = part * 32 + jj;
        float v  = Csh[m_of][col] * scB[col];
        int  gn  = n0 + col;
        if (v > bestv) { bestv = v; besti = gn; }       // ascending -> first max on ties
    }
    // merge lane pairs (2t, 2t+1 share m)
    float ov = __shfl_xor_sync(0xffffffffu, bestv, 1);
    int   oi = __shfl_xor_sync(0xffffffffu, besti, 1);
    if (ov > bestv || (ov == bestv && oi < besti)) { bestv = ov; besti = oi; }
    if (part == 0) {
        unsigned long long key =
            ((unsigned long long)ordered_f32(bestv) << 32) |
            (unsigned)(0x7FFFFFFFu - besti);
        atomicMax(&g_best[b * MM + m_of], key);
    }
}

// ---------------------------------------------------------------------------
// K3: loss. One warp per (b,t): d_pos, d_neg (exact fp32), relu, atomicAdd.
// ---------------------------------------------------------------------------
__global__ __launch_bounds__(256) void k3_loss(const float* __restrict__ emb,
                                               const int* __restrict__ muc,
                                               const int* __restrict__ non,
                                               const int* __restrict__ anc,
                                               const int* __restrict__ pos,
                                               float* __restrict__ out) {
    int g    = blockIdx.x * blockDim.x + threadIdx.x;
    int w    = g >> 5;
    int lane = g & 31;
    if (w >= BB * TT) return;
    int b = w / TT;
    int t = w % TT;

    int m  = anc[b * TT + t];
    int ra = muc[b * MM + m];
    int rp = muc[b * MM + pos[b * TT + t]];

    unsigned long long key = g_best[b * MM + m];
    int n  = (int)(0x7FFFFFFFu - (unsigned)(key & 0xFFFFFFFFu));
    int rn = non[b * NNEG + n];

    const float4* pa = reinterpret_cast<const float4*>(emb + ((size_t)b * CC + ra) * DD);
    const float4* pp = reinterpret_cast<const float4*>(emb + ((size_t)b * CC + rp) * DD);
    const float4* pn = reinterpret_cast<const float4*>(emb + ((size_t)b * CC + rn) * DD);
    float ia  = g_inv[b * CC + ra];
    float ip  = g_inv[b * CC + rp];
    float in_ = g_inv[b * CC + rn];

    float ssp = 0.0f, ssn = 0.0f;
#pragma unroll
    for (int q = 0; q < 4; q++) {
        int o = lane + 32 * q;
        float4 va = pa[o];
        float4 vp = pp[o];
        float4 vn = pn[o];
        float d;
        d = va.x * ia - vp.x * ip + EPS;  ssp = fmaf(d, d, ssp);
        d = va.y * ia - vp.y * ip + EPS;  ssp = fmaf(d, d, ssp);
        d = va.z * ia - vp.z * ip + EPS;  ssp = fmaf(d, d, ssp);
        d = va.w * ia - vp.w * ip + EPS;  ssp = fmaf(d, d, ssp);
        d = va.x * ia - vn.x * in_ + EPS; ssn = fmaf(d, d, ssn);
        d = va.y * ia - vn.y * in_ + EPS; ssn = fmaf(d, d, ssn);
        d = va.z * ia - vn.z * in_ + EPS; ssn = fmaf(d, d, ssn);
        d = va.w * ia - vn.w * in_ + EPS; ssn = fmaf(d, d, ssn);
    }
#pragma unroll
    for (int off = 16; off; off >>= 1) {
        ssp += __shfl_xor_sync(0xffffffffu, ssp, off);
        ssn += __shfl_xor_sync(0xffffffffu, ssn, off);
    }
    if (lane == 0) {
        float term = sqrtf(ssp) - sqrtf(ssn) + 1.0f;   // margin = 1.0
        term = fmaxf(term, 0.0f);
        atomicAdd(out, term * (1.0f / (float)(BB * TT)));
    }
}

// ---------------------------------------------------------------------------
extern "C" void kernel_launch(void* const* d_in, const int* in_sizes, int n_in,
                              void* d_out, int out_size) {
    const float* emb = (const float*)d_in[0];
    const int*   muc = (const int*)d_in[1];
    const int*   non = (const int*)d_in[2];
    const int*   anc = (const int*)d_in[3];
    const int*   pos = (const int*)d_in[4];
    float* out = (float*)d_out;

    k0_init<<<(BB * MM + 255) / 256, 256>>>(out);
    k1_norm<<<(BB * CC) / 8, 256>>>(emb);
    dim3 g2(NNEG / NT, BB);
    k2_mine<<<g2, 256>>>(emb, muc, non);
    k3_loss<<<(BB * TT * 32 + 255) / 256, 256>>>(emb, muc, non, anc, pos, out);
}